// round 15
// baseline (speedup 1.0000x reference)
#include <cuda_runtime.h>
#include <cstdint>

// p-bit Glauber, N=4096, 16384 steps. Segment architecture v4:
//  - SS=512, 32 segments; step-pair table g_T = 33.5MB -> unconditionally
//    L2-resident. The sequential engine NEVER touches J; folders stream J
//    with __ldcs so T stays resident.
//  - ONE persistent kernel (grid=9): block0 = sequential engine (evaluator
//    warp + 512 G-keepers, one step each, scalar G); blocks 1..8 = streaming
//    fold engine (g_F[col] in a register) consuming flips PER WINDOW via a
//    release/acquire pubCnt counter -> fold overlaps its own segment, the
//    segment-boundary wait is only the last window's tail.
//  - handshake: evaluator publishes g_fl + pubCnt per window (fence+atomic);
//    at segment end cum[s] + segReady; folders apply, write g_F, foldDone+=1;
//    seq engine waits foldDone>=8*s before G-init of segment s.

#define NN      4096
#define NSTEPS  16384
#define W       64
#define SS      512
#define WPS     (SS / W)        // 8
#define NSEG    (NSTEPS / SS)   // 32
#define TPB     544
#define FULLM   0xffffffffu

__device__ float  g_F[NN];
__device__ float2 g_TI[NSTEPS];
__device__ int    g_fl[NSTEPS];      // global flip stream: spin | sign<<30
__device__ int    g_cum[NSEG];       // cumulative flip count at segment end
__device__ int    g_pubCnt;
__device__ int    g_segReady;
__device__ int    g_foldDone;
__device__ float  g_T[(size_t)NSEG * SS * SS];   // 33.5MB, L2-resident

struct Sm {
    float Tw[2][W * W];     // 32KB
    float Tc[2][W * W];     // 32KB
    float Gpub[2][W];
    int   flist[2][W];      // segment-local step | sign<<30
    int   fcnt[2];
    signed char m[NN];      // 4KB, persists across segments
};
#define SMEM_BYTES ((int)sizeof(Sm))

__device__ __forceinline__ int ld_acq(const int* p) {
    int v;
    asm volatile("ld.acquire.gpu.s32 %0, [%1];" : "=r"(v) : "l"(p) : "memory");
    return v;
}

// ---------------------------------------------------------------------------
// fused prep: pack_T | init_F | thresholds + flag reset. J reads streamed.
// ---------------------------------------------------------------------------
__global__ void prep_all(const float* __restrict__ J,
                         const float* __restrict__ h,
                         const float* __restrict__ m0,
                         const int*   __restrict__ idx,
                         const float* __restrict__ u) {
    const int bid = blockIdx.x;
    if (bid < NSEG * SS) {
        __shared__ float rowS[NN];
        __shared__ int   ids[SS];
        const int s  = bid / SS;
        const int tp = bid % SS;
        const int rowIdx = idx[bid];
        const float4* __restrict__ Jr =
            reinterpret_cast<const float4*>(J) + (size_t)rowIdx * (NN / 4);
        for (int k = threadIdx.x; k < NN / 4; k += 256)
            reinterpret_cast<float4*>(rowS)[k] = __ldcs(&Jr[k]);
        for (int k = threadIdx.x; k < SS; k += 256)
            ids[k] = idx[s * SS + k];
        __syncthreads();
        float* __restrict__ dst = g_T + (size_t)s * SS * SS + (size_t)tp * SS;
        dst[threadIdx.x]       = rowS[ids[threadIdx.x]];
        dst[threadIdx.x + 256] = rowS[ids[threadIdx.x + 256]];
    } else if (bid < NSEG * SS + NN) {
        const int row = bid - NSEG * SS;
        const float4* __restrict__ Jr =
            reinterpret_cast<const float4*>(J) + (size_t)row * (NN / 4);
        const float4* __restrict__ M4 = reinterpret_cast<const float4*>(m0);
        float sum = 0.0f;
        for (int k = threadIdx.x; k < NN / 4; k += 256) {
            float4 a = __ldcs(&Jr[k]);
            float4 b = M4[k];
            sum += a.x * b.x + a.y * b.y + a.z * b.z + a.w * b.w;
        }
        #pragma unroll
        for (int off = 16; off; off >>= 1)
            sum += __shfl_xor_sync(FULLM, sum, off);
        __shared__ float ws[8];
        const int lane = threadIdx.x & 31;
        const int wid  = threadIdx.x >> 5;
        if (lane == 0) ws[wid] = sum;
        __syncthreads();
        if (threadIdx.x == 0) {
            float tot = 0.0f;
            #pragma unroll
            for (int w = 0; w < 8; w++) tot += ws[w];
            g_F[row] = tot + h[row];
        }
    } else {
        const int b = bid - NSEG * SS - NN;
        const int t = b * 256 + threadIdx.x;
        const float r = 2.0f * u[t] - 1.0f;
        g_TI[t] = make_float2(atanhf(r), __int_as_float(idx[t]));
        if (b == 0 && threadIdx.x == 0) {
            g_segReady = 0;
            g_foldDone = 0;
            g_pubCnt   = 0;
        }
    }
}

// ---------------------------------------------------------------------------
__global__ __launch_bounds__(TPB, 1)
void pbit_dynamics(const float* __restrict__ J,
                   const float* __restrict__ m0,
                   float*       __restrict__ out) {
    extern __shared__ char raw[];
    Sm* S = reinterpret_cast<Sm*>(raw);

    const int tid  = threadIdx.x;
    const int lane = tid & 31;

    if (blockIdx.x != 0) {
        // ================= streaming fold engine (blocks 1..8) ===============
        __shared__ int sAvail, sCum;
        const int col = (blockIdx.x - 1) * 512 + (tid & 511);
        float fcol = __ldcg(&g_F[col]);
        int applied = 0;
        for (int s = 0; s < NSEG - 1; s++) {
            for (;;) {
                if (tid == 0) {
                    sAvail = ld_acq(&g_pubCnt);
                    const int sr = ld_acq(&g_segReady);
                    sCum = (sr > s) ? *(volatile int*)&g_cum[s] : -1;
                }
                __syncthreads();
                const int tgt = (sCum >= 0) ? sCum : sAvail;
                if (tid < 512) {
                    int k = applied;
                    for (; k + 16 <= tgt; k += 16) {
                        float v[16], d[16];
                        #pragma unroll
                        for (int j = 0; j < 16; j++) {
                            const int e = __ldcg(&g_fl[k + j]);
                            d[j] = (e & (1 << 30)) ? 2.0f : -2.0f;
                            v[j] = __ldcs(J + (size_t)(e & 0xFFFF) * NN + col);
                        }
                        #pragma unroll
                        for (int j = 0; j < 16; j++)
                            fcol = fmaf(v[j], d[j], fcol);
                    }
                    for (; k < tgt; k++) {
                        const int e = __ldcg(&g_fl[k]);
                        const float d = (e & (1 << 30)) ? 2.0f : -2.0f;
                        fcol = fmaf(__ldcs(J + (size_t)(e & 0xFFFF) * NN + col), d, fcol);
                    }
                }
                applied = tgt;
                const bool done = (sCum >= 0) && (applied >= sCum);
                __syncthreads();
                if (done) break;
            }
            if (tid < 512) g_F[col] = fcol;
            __threadfence();
            __syncthreads();
            if (tid == 0) atomicAdd(&g_foldDone, 1);
        }
        return;
    }

    // ===================== sequential engine (block 0) =======================
    const bool is_ev = (tid < 32);
    const int kid   = tid - 32;            // keeper id == owned local step
    int gGlob = 0;

    for (int k = tid; k < NN; k += TPB)
        S->m[k] = (m0[k] > 0.0f) ? 1 : -1;

    for (int s = 0; s < NSEG; s++) {
        const int segBase = s * SS;
        const float* __restrict__ Tseg = g_T + (size_t)s * SS * SS;

        if (tid == 0) { S->fcnt[0] = 0; S->fcnt[1] = 0; }

        // prologue staging (fold-independent): Tw[0]
        if (!is_ev) {
            const int krow  = kid >> 3;
            const int lbase = (kid & 7) * 8;
            const float* wsrc = Tseg + (size_t)krow * SS + lbase;
            float4 wa = *reinterpret_cast<const float4*>(wsrc);
            float4 wb = *reinterpret_cast<const float4*>(wsrc + 4);
            *reinterpret_cast<float4*>(&S->Tw[0][krow * W + lbase])     = wa;
            *reinterpret_cast<float4*>(&S->Tw[0][krow * W + lbase + 4]) = wb;
        }

        // wait for fold of segment s-1
        if (s > 0) {
            if (tid == 0)
                while (ld_acq(&g_foldDone) < 8 * s) { }
            __syncthreads();
        }

        float Greg = 0.0f;
        float2 tiPF0 = make_float2(0.f, 0.f), tiPF1 = tiPF0;
        unsigned prevM0 = 0, prevS0 = 0, prevM1 = 0, prevS1 = 0;

        if (is_ev) {
            tiPF0 = g_TI[segBase + lane];
            tiPF1 = g_TI[segBase + 32 + lane];
        } else {
            const float2 a = g_TI[segBase + kid];
            Greg = __ldcg(&g_F[__float_as_int(a.y)]);
            if (kid < W) S->Gpub[0][kid] = Greg;
        }
        __syncthreads();

        for (int p = 0; p < WPS; p++) {
            const int par = p & 1;
            if (is_ev) {
                // ================= evaluator =================
                const float thr0 = tiPF0.x;
                const int   i0   = __float_as_int(tiPF0.y);
                const float thr1 = tiPF1.x;
                const int   i1x  = __float_as_int(tiPF1.y);
                float f0  = S->Gpub[par][lane];
                float f1v = S->Gpub[par][32 + lane];
                bool pos0 = (S->m[i0]  > 0);
                bool pos1 = (S->m[i1x] > 0);
                if (p + 1 < WPS) {
                    tiPF0 = g_TI[segBase + (p + 1) * W + lane];
                    tiPF1 = g_TI[segBase + (p + 1) * W + 32 + lane];
                }

                // catch up window p-1's flips
                const float* TcP = S->Tc[par];
                {
                    unsigned mm = prevM0;
                    while (mm) {
                        const int k = __ffs(mm) - 1;
                        mm &= mm - 1;
                        const float dk = ((prevS0 >> k) & 1u) ? 2.0f : -2.0f;
                        f0  = fmaf(TcP[(k << 6) + lane],      dk, f0);
                        f1v = fmaf(TcP[(k << 6) + 32 + lane], dk, f1v);
                    }
                    mm = prevM1;
                    while (mm) {
                        const int k = __ffs(mm) - 1;
                        mm &= mm - 1;
                        const int r = 32 + k;
                        const float dk = ((prevS1 >> k) & 1u) ? 2.0f : -2.0f;
                        f0  = fmaf(TcP[(r << 6) + lane],      dk, f0);
                        f1v = fmaf(TcP[(r << 6) + 32 + lane], dk, f1v);
                    }
                }

                const float* TwP = S->Tw[par];
                unsigned nM0 = 0, nS0 = 0, nM1 = 0, nS1 = 0;
                int cnt = 0;
                const int base = gGlob;

                // half A
                {
                    bool sp = (f0 >= thr0);
                    bool fl = sp != pos0;
                    unsigned fb  = __ballot_sync(FULLM, fl);
                    unsigned sbm = __ballot_sync(FULLM, sp);
                    while (fb) {
                        const int  f = __ffs(fb) - 1;
                        const bool s1 = (sbm >> f) & 1u;
                        const float d = s1 ? 2.0f : -2.0f;
                        const float jva = TwP[(f << 6) + lane];
                        const float jvb = TwP[(f << 6) + 32 + lane];
                        const int   ii  = __shfl_sync(FULLM, i0, f);
                        if (lane == f) {
                            S->m[ii] = s1 ? 1 : -1;
                            const int sg = s1 ? (1 << 30) : 0;
                            S->flist[par][cnt] = (p * W + f) | sg;
                            g_fl[base + cnt]   = ii | sg;
                        }
                        nM0 |= 1u << f;
                        if (s1) nS0 |= 1u << f;
                        cnt++;
                        f0  = fmaf(jva, d, f0);
                        f1v = fmaf(jvb, d, f1v);
                        if (i0  == ii) pos0 = s1;
                        if (i1x == ii) pos1 = s1;
                        bool ns = false, nf2 = false;
                        if (lane > f) {
                            ns  = (f0 >= thr0);
                            nf2 = ns != pos0;
                        }
                        fb  = __ballot_sync(FULLM, nf2);
                        sbm = __ballot_sync(FULLM, ns);
                    }
                }
                // half B
                {
                    bool sp = (f1v >= thr1);
                    bool fl = sp != pos1;
                    unsigned fb  = __ballot_sync(FULLM, fl);
                    unsigned sbm = __ballot_sync(FULLM, sp);
                    while (fb) {
                        const int  f = __ffs(fb) - 1;
                        const bool s1 = (sbm >> f) & 1u;
                        const float d = s1 ? 2.0f : -2.0f;
                        const int  r = 32 + f;
                        const float jvb = TwP[(r << 6) + 32 + lane];
                        const int   ii  = __shfl_sync(FULLM, i1x, f);
                        if (lane == f) {
                            S->m[ii] = s1 ? 1 : -1;
                            const int sg = s1 ? (1 << 30) : 0;
                            S->flist[par][cnt] = (p * W + 32 + f) | sg;
                            g_fl[base + cnt]   = ii | sg;
                        }
                        nM1 |= 1u << f;
                        if (s1) nS1 |= 1u << f;
                        cnt++;
                        f1v = fmaf(jvb, d, f1v);
                        if (i1x == ii) pos1 = s1;
                        bool ns = false, nf2 = false;
                        if (lane > f) {
                            ns  = (f1v >= thr1);
                            nf2 = ns != pos1;
                        }
                        fb  = __ballot_sync(FULLM, nf2);
                        sbm = __ballot_sync(FULLM, ns);
                    }
                }
                if (lane == 0) S->fcnt[par] = cnt;
                gGlob = base + cnt;
                // publish this window's flips to the fold engine
                __syncwarp();
                __threadfence();
                if (lane == 0) atomicExch(&g_pubCnt, gGlob);
                prevM0 = nM0; prevS0 = nS0;
                prevM1 = nM1; prevS1 = nS1;
            } else {
                // ================= keepers (one step each) =================
                const bool hasNext = (p + 1 < WPS);
                const int krow  = kid >> 3;
                const int lbase = (kid & 7) * 8;
                float4 wa, wb, ca, cb;
                if (hasNext) {
                    const float* wsrc =
                        Tseg + (size_t)((p + 1) * W + krow) * SS + (p + 1) * W + lbase;
                    const float* csrc =
                        Tseg + (size_t)(p * W + krow) * SS + (p + 1) * W + lbase;
                    wa = *reinterpret_cast<const float4*>(wsrc);
                    wb = *reinterpret_cast<const float4*>(wsrc + 4);
                    ca = *reinterpret_cast<const float4*>(csrc);
                    cb = *reinterpret_cast<const float4*>(csrc + 4);
                }

                // apply window p-1's flips to future-owned G (batch 16)
                const int np = S->fcnt[par ^ 1];
                const int* fl = S->flist[par ^ 1];
                const bool active = (kid >= (p + 1) * W);
                for (int kb = 0; kb < np; kb += 16) {
                    float dd[16], v[16];
                    #pragma unroll
                    for (int j = 0; j < 16; j++) {
                        const bool vld = (kb + j < np);
                        const int e = vld ? fl[kb + j] : 0;
                        dd[j] = vld ? ((e & (1 << 30)) ? 2.0f : -2.0f) : 0.0f;
                        const int tp2 = e & 0xFFFF;
                        v[j] = (vld && active)
                            ? Tseg[(size_t)tp2 * SS + kid] : 0.0f;
                    }
                    #pragma unroll
                    for (int j = 0; j < 16; j++)
                        Greg = fmaf(v[j], dd[j], Greg);
                }

                if (hasNext) {
                    *reinterpret_cast<float4*>(&S->Tw[par ^ 1][krow * W + lbase])     = wa;
                    *reinterpret_cast<float4*>(&S->Tw[par ^ 1][krow * W + lbase + 4]) = wb;
                    *reinterpret_cast<float4*>(&S->Tc[par ^ 1][krow * W + lbase])     = ca;
                    *reinterpret_cast<float4*>(&S->Tc[par ^ 1][krow * W + lbase + 4]) = cb;
                    if ((kid >> 6) == p + 1)
                        S->Gpub[par ^ 1][kid & (W - 1)] = Greg;
                }
            }
            __syncthreads();
        }

        // segment epilogue: cum + segReady (release)
        if (is_ev) {
            if (lane == 0) g_cum[s] = gGlob;
            __syncwarp();
            __threadfence();
            if (lane == 0 && s + 1 < NSEG) atomicExch(&g_segReady, s + 1);
        }
        __syncthreads();
    }

    for (int k = tid; k < NN; k += TPB)
        out[k] = (float)S->m[k];
}

// ---------------------------------------------------------------------------
extern "C" void kernel_launch(void* const* d_in, const int* in_sizes, int n_in,
                              void* d_out, int out_size) {
    const float* J  = (const float*)d_in[0];
    const float* h  = (const float*)d_in[1];
    const float* m0 = (const float*)d_in[2];
    const int*   idx= (const int*)  d_in[3];
    const float* u  = (const float*)d_in[4];
    float* out = (float*)d_out;

    cudaFuncSetAttribute(pbit_dynamics,
                         cudaFuncAttributeMaxDynamicSharedMemorySize,
                         SMEM_BYTES);

    const int prepBlocks = NSEG * SS + NN + NSTEPS / 256;
    prep_all<<<prepBlocks, 256>>>(J, h, m0, idx, u);
    pbit_dynamics<<<9, TPB, SMEM_BYTES>>>(J, m0, out);
}

// round 16
// speedup vs baseline: 1.2651x; 1.2651x over previous
#include <cuda_runtime.h>
#include <cstdint>

// p-bit Glauber, N=4096, 16384 steps — R10 architecture + owner-L1 shaving.
// prep_all (one launch): F0 = J@m0+h | per-window tables (W=64):
//   Jw[w][k][l]=J[idx(w,k)][idx(w,l)], Jc[w][k][l]=J[idx(w-1,k)][idx(w,l)]
//   | thr=atanh(2u-1) zipped with idx.
// pbit_dynamics: single CTA, 544 threads, warp-specialized, 256 windows:
//   evaluator (warp 0): resolves window p from smem Jw; catch-up of window
//     p-1's flips reads Jc DIRECTLY FROM GLOBAL (chunked prefetch, coalesced,
//     L2-resident) -> owners no longer stage Jc (saves 32KB/window of L1).
//   owners (512 thr, F in registers, 8 elems/thread): stage Jw(p+1) early,
//     apply window p-1's flip list (rank-1 J rows, batch 6), publish F_sh.
//   ONE __syncthreads per window + named-barrier handshake.

#define NN      4096
#define NSTEPS  16384
#define W       64
#define NWIN    (NSTEPS / W)      // 256
#define TPB     544
#define NOWN    512
#define FULLM   0xffffffffu

__device__ float  g_F[NN];
__device__ float2 g_TI[NSTEPS];
__device__ float  g_Jw[NWIN * W * W];   // 4MB
__device__ float  g_Jc[NWIN * W * W];   // 4MB (read by evaluator from global)

struct Sm {
    float F[NN];              // 16KB
    float Jw[2][W * W];       // 32KB
    signed char m[NN];        // 4KB
    int   flist[2][W];
    int   fcnt[2];
};
#define SMEM_BYTES ((int)sizeof(Sm))

// ---------------------------------------------------------------------------
// fused prep: init_field rows | pack window tables | thresholds
// ---------------------------------------------------------------------------
__global__ void prep_all(const float* __restrict__ J,
                         const float* __restrict__ h,
                         const float* __restrict__ m0,
                         const int*   __restrict__ idx,
                         const float* __restrict__ u) {
    const int bid = blockIdx.x;
    if (bid < NN) {
        // ---- init_field row ----
        const int row = bid;
        const float4* __restrict__ Jr =
            reinterpret_cast<const float4*>(J) + (size_t)row * (NN / 4);
        const float4* __restrict__ M4 = reinterpret_cast<const float4*>(m0);
        float sum = 0.0f;
        for (int k = threadIdx.x; k < NN / 4; k += 256) {
            float4 a = Jr[k];
            float4 b = M4[k];
            sum += a.x * b.x + a.y * b.y + a.z * b.z + a.w * b.w;
        }
        #pragma unroll
        for (int off = 16; off; off >>= 1)
            sum += __shfl_xor_sync(FULLM, sum, off);
        __shared__ float ws[8];
        const int lane = threadIdx.x & 31;
        const int wid  = threadIdx.x >> 5;
        if (lane == 0) ws[wid] = sum;
        __syncthreads();
        if (threadIdx.x == 0) {
            float tot = 0.0f;
            #pragma unroll
            for (int w = 0; w < 8; w++) tot += ws[w];
            g_F[row] = tot + h[row];
        }
    } else if (bid < NN + NWIN) {
        // ---- pack window tables ----
        const int w = bid - NN;
        for (int e = threadIdx.x; e < W * W; e += 256) {
            const int k = e >> 6;
            const int l = e & 63;
            const int il = idx[w * W + l];
            const int ik = idx[w * W + k];
            g_Jw[(size_t)w * W * W + e] = J[(size_t)ik * NN + il];
            float jc = 0.0f;
            if (w > 0) {
                const int ikp = idx[(w - 1) * W + k];
                jc = J[(size_t)ikp * NN + il];
            }
            g_Jc[(size_t)w * W * W + e] = jc;
        }
    } else {
        // ---- thresholds ----
        const int t = (bid - NN - NWIN) * 256 + threadIdx.x;
        if (t < NSTEPS) {
            const float r = 2.0f * u[t] - 1.0f;
            g_TI[t] = make_float2(atanhf(r), __int_as_float(idx[t]));
        }
    }
}

// ---------------------------------------------------------------------------
__global__ __launch_bounds__(TPB, 1)
void pbit_dynamics(const float* __restrict__ J,
                   const float* __restrict__ m0,
                   float*       __restrict__ out) {
    extern __shared__ char smraw[];
    Sm* S = reinterpret_cast<Sm*>(smraw);

    const int tid  = threadIdx.x;
    const int lane = tid & 31;
    const bool is_ev = (tid < 32);
    const int oid  = tid - 32;      // owner index [0,512)

    // ---- init ----
    const float4* gF4 = reinterpret_cast<const float4*>(g_F);
    float4* F4 = reinterpret_cast<float4*>(S->F);
    float4 Fa, Fb;
    if (!is_ev) {
        Fa = gF4[oid];
        Fb = gF4[oid + NOWN];
        F4[oid]        = Fa;
        F4[oid + NOWN] = Fb;
    }
    for (int k = tid; k < NN; k += TPB)
        S->m[k] = (m0[k] > 0.0f) ? 1 : -1;
    if (tid == 0) { S->fcnt[0] = 0; S->fcnt[1] = 0; }
    for (int e = tid; e < W * W; e += TPB)         // stage window 0
        S->Jw[0][e] = g_Jw[e];
    float2 tiPF0 = make_float2(0.f, 0.f), tiPF1 = tiPF0;
    if (is_ev) {
        tiPF0 = g_TI[lane];
        tiPF1 = g_TI[32 + lane];
    }
    unsigned prevM0 = 0, prevS0 = 0, prevM1 = 0, prevS1 = 0;
    __syncthreads();

    for (int p = 0; p < NWIN; p++) {
        const int par = p & 1;
        if (is_ev) {
            // ================= evaluator =================
            const float thr0 = tiPF0.x;
            const int   i0   = __float_as_int(tiPF0.y);
            const float thr1 = tiPF1.x;
            const int   i1x  = __float_as_int(tiPF1.y);
            float f0  = S->F[i0];            // state <= p-2
            float f1v = S->F[i1x];
            bool pos0 = (S->m[i0]  > 0);
            bool pos1 = (S->m[i1x] > 0);
            asm volatile("bar.arrive 1, %0;" :: "r"(TPB));   // release F_sh

            if (p + 1 < NWIN) {
                tiPF0 = g_TI[(p + 1) * W + lane];
                tiPF1 = g_TI[(p + 1) * W + 32 + lane];
            }

            // ---- catch up window p-1's flips from GLOBAL Jc (chunks of 8,
            //      loads prefetched, fmaf in chronological order) ----
            const float* __restrict__ JcG = g_Jc + (size_t)p * (W * W);
            {
                unsigned mm = prevM0;
                while (mm) {
                    float v0[8], v1[8], dd[8];
                    #pragma unroll
                    for (int j = 0; j < 8; j++) {
                        if (mm) {
                            const int k = __ffs(mm) - 1;
                            mm &= mm - 1;
                            v0[j] = __ldg(&JcG[(k << 6) + lane]);
                            v1[j] = __ldg(&JcG[(k << 6) + 32 + lane]);
                            dd[j] = ((prevS0 >> k) & 1u) ? 2.0f : -2.0f;
                        } else { v0[j] = 0.f; v1[j] = 0.f; dd[j] = 0.f; }
                    }
                    #pragma unroll
                    for (int j = 0; j < 8; j++) {
                        f0  = fmaf(v0[j], dd[j], f0);
                        f1v = fmaf(v1[j], dd[j], f1v);
                    }
                }
                mm = prevM1;
                while (mm) {
                    float v0[8], v1[8], dd[8];
                    #pragma unroll
                    for (int j = 0; j < 8; j++) {
                        if (mm) {
                            const int k = __ffs(mm) - 1;
                            mm &= mm - 1;
                            const int r = 32 + k;
                            v0[j] = __ldg(&JcG[(r << 6) + lane]);
                            v1[j] = __ldg(&JcG[(r << 6) + 32 + lane]);
                            dd[j] = ((prevS1 >> k) & 1u) ? 2.0f : -2.0f;
                        } else { v0[j] = 0.f; v1[j] = 0.f; dd[j] = 0.f; }
                    }
                    #pragma unroll
                    for (int j = 0; j < 8; j++) {
                        f0  = fmaf(v0[j], dd[j], f0);
                        f1v = fmaf(v1[j], dd[j], f1v);
                    }
                }
            }

            const float* TwP = S->Jw[par];
            unsigned nM0 = 0, nS0 = 0, nM1 = 0, nS1 = 0;
            int cnt = 0;

            // ---- half A: steps 0..31 ----
            {
                bool sp = (f0 >= thr0);
                bool fl = sp != pos0;
                unsigned fb  = __ballot_sync(FULLM, fl);
                unsigned sbm = __ballot_sync(FULLM, sp);
                while (fb) {
                    const int  f = __ffs(fb) - 1;
                    const bool s1 = (sbm >> f) & 1u;
                    const float d = s1 ? 2.0f : -2.0f;
                    const float jva = TwP[(f << 6) + lane];
                    const float jvb = TwP[(f << 6) + 32 + lane];
                    const int   ii  = __shfl_sync(FULLM, i0, f);
                    if (lane == f) {
                        S->m[ii] = s1 ? 1 : -1;
                        S->flist[par][cnt] = ii | (s1 ? (1 << 30) : 0);
                    }
                    nM0 |= 1u << f;
                    if (s1) nS0 |= 1u << f;
                    cnt++;
                    f0  = fmaf(jva, d, f0);
                    f1v = fmaf(jvb, d, f1v);
                    if (i0  == ii) pos0 = s1;
                    if (i1x == ii) pos1 = s1;
                    bool ns = false, nf2 = false;
                    if (lane > f) {
                        ns  = (f0 >= thr0);
                        nf2 = ns != pos0;
                    }
                    fb  = __ballot_sync(FULLM, nf2);
                    sbm = __ballot_sync(FULLM, ns);
                }
            }
            // ---- half B: steps 32..63 ----
            {
                bool sp = (f1v >= thr1);
                bool fl = sp != pos1;
                unsigned fb  = __ballot_sync(FULLM, fl);
                unsigned sbm = __ballot_sync(FULLM, sp);
                while (fb) {
                    const int  f = __ffs(fb) - 1;
                    const bool s1 = (sbm >> f) & 1u;
                    const float d = s1 ? 2.0f : -2.0f;
                    const int  r = 32 + f;
                    const float jvb = TwP[(r << 6) + 32 + lane];
                    const int   ii  = __shfl_sync(FULLM, i1x, f);
                    if (lane == f) {
                        S->m[ii] = s1 ? 1 : -1;
                        S->flist[par][cnt] = ii | (s1 ? (1 << 30) : 0);
                    }
                    nM1 |= 1u << f;
                    if (s1) nS1 |= 1u << f;
                    cnt++;
                    f1v = fmaf(jvb, d, f1v);
                    if (i1x == ii) pos1 = s1;
                    bool ns = false, nf2 = false;
                    if (lane > f) {
                        ns  = (f1v >= thr1);
                        nf2 = ns != pos1;
                    }
                    fb  = __ballot_sync(FULLM, nf2);
                    sbm = __ballot_sync(FULLM, ns);
                }
            }
            if (lane == 0) S->fcnt[par] = cnt;
            prevM0 = nM0; prevS0 = nS0;
            prevM1 = nM1; prevS1 = nS1;
        } else {
            // ================= owners =================
            // issue Jw staging loads for window p+1 FIRST (latency hidden)
            float4 sw0, sw1;
            const bool hasStage = (p + 1 < NWIN);
            if (hasStage) {
                const float4* __restrict__ sw =
                    reinterpret_cast<const float4*>(g_Jw + (size_t)(p + 1) * (W * W));
                sw0 = sw[oid];
                sw1 = sw[oid + NOWN];
            }

            // apply window p-1's flips (batch 6)
            const int np = S->fcnt[par ^ 1];
            for (int kb = 0; kb < np; kb += 6) {
                float  dd[6];
                float4 r0[6], r1[6];
                #pragma unroll
                for (int j = 0; j < 6; j++) {
                    const bool v = (kb + j < np);
                    const int e = v ? S->flist[par ^ 1][kb + j] : 0;
                    dd[j] = v ? ((e & (1 << 30)) ? 2.0f : -2.0f) : 0.0f;
                    const int ik = e & 0xFFFF;
                    const float4* __restrict__ Jr =
                        reinterpret_cast<const float4*>(J) + (size_t)ik * (NN / 4);
                    if (v) {
                        r0[j] = Jr[oid];
                        r1[j] = Jr[oid + NOWN];
                    } else {
                        r0[j] = make_float4(0.f, 0.f, 0.f, 0.f);
                        r1[j] = r0[j];
                    }
                }
                #pragma unroll
                for (int j = 0; j < 6; j++) {
                    Fa.x = fmaf(r0[j].x, dd[j], Fa.x);
                    Fa.y = fmaf(r0[j].y, dd[j], Fa.y);
                    Fa.z = fmaf(r0[j].z, dd[j], Fa.z);
                    Fa.w = fmaf(r0[j].w, dd[j], Fa.w);
                    Fb.x = fmaf(r1[j].x, dd[j], Fb.x);
                    Fb.y = fmaf(r1[j].y, dd[j], Fb.y);
                    Fb.z = fmaf(r1[j].z, dd[j], Fb.z);
                    Fb.w = fmaf(r1[j].w, dd[j], Fb.w);
                }
            }

            // store Jw staging into the buffer freed last window
            if (hasStage) {
                float4* dw = reinterpret_cast<float4*>(S->Jw[par ^ 1]);
                dw[oid]        = sw0;
                dw[oid + NOWN] = sw1;
            }

            // wait for evaluator's F_sh reads, then publish
            asm volatile("bar.sync 1, %0;" :: "r"(TPB));
            if (np > 0) {
                F4[oid]        = Fa;
                F4[oid + NOWN] = Fb;
            }
        }
        __syncthreads();
    }

    for (int k = tid; k < NN; k += TPB)
        out[k] = (float)S->m[k];
}

// ---------------------------------------------------------------------------
extern "C" void kernel_launch(void* const* d_in, const int* in_sizes, int n_in,
                              void* d_out, int out_size) {
    const float* J  = (const float*)d_in[0];
    const float* h  = (const float*)d_in[1];
    const float* m0 = (const float*)d_in[2];
    const int*   idx= (const int*)  d_in[3];
    const float* u  = (const float*)d_in[4];
    float* out = (float*)d_out;

    static bool attrSet = false;
    if (!attrSet) {
        cudaFuncSetAttribute(pbit_dynamics,
                             cudaFuncAttributeMaxDynamicSharedMemorySize,
                             SMEM_BYTES);
        attrSet = true;
    }

    const int prepBlocks = NN + NWIN + (NSTEPS + 255) / 256;
    prep_all<<<prepBlocks, 256>>>(J, h, m0, idx, u);
    pbit_dynamics<<<1, TPB, SMEM_BYTES>>>(J, m0, out);
}

// round 17
// speedup vs baseline: 1.5689x; 1.2401x over previous
#include <cuda_runtime.h>
#include <cstdint>

// p-bit Glauber, N=4096, 16384 steps — R10 architecture, owner batch 8.
// prep_all (one launch): F0 = J@m0+h | per-window tables (W=64):
//   Jw[w][k][l]=J[idx(w,k)][idx(w,l)], Jc[w][k][l]=J[idx(w-1,k)][idx(w,l)]
//   | thr=atanh(2u-1) zipped with idx.
// pbit_dynamics: single CTA, 544 threads, warp-specialized, 256 windows:
//   evaluator (warp 0): resolves window p (two 32-step halves) from smem Jw;
//     catch-up of window p-1's flips via smem Jc (chronological order).
//   owners (512 thr, F in registers, 8 elems/thread): stage Jw/Jc(p+1) early,
//     apply window p-1's flip list with batch-8 MLP (16 LDG.128 in flight),
//     publish F_sh after named-barrier handshake. ONE __syncthreads/window.

#define NN      4096
#define NSTEPS  16384
#define W       64
#define NWIN    (NSTEPS / W)      // 256
#define TPB     544
#define NOWN    512
#define FULLM   0xffffffffu

__device__ float  g_F[NN];
__device__ float2 g_TI[NSTEPS];
__device__ float  g_Jw[NWIN * W * W];   // 4MB
__device__ float  g_Jc[NWIN * W * W];   // 4MB

struct Sm {
    float F[NN];              // 16KB
    float Jw[2][W * W];       // 32KB
    float Jc[2][W * W];       // 32KB
    signed char m[NN];        // 4KB
    int   flist[2][W];
    int   fcnt[2];
};
#define SMEM_BYTES ((int)sizeof(Sm))

// ---------------------------------------------------------------------------
__global__ void prep_all(const float* __restrict__ J,
                         const float* __restrict__ h,
                         const float* __restrict__ m0,
                         const int*   __restrict__ idx,
                         const float* __restrict__ u) {
    const int bid = blockIdx.x;
    if (bid < NN) {
        const int row = bid;
        const float4* __restrict__ Jr =
            reinterpret_cast<const float4*>(J) + (size_t)row * (NN / 4);
        const float4* __restrict__ M4 = reinterpret_cast<const float4*>(m0);
        float sum = 0.0f;
        for (int k = threadIdx.x; k < NN / 4; k += 256) {
            float4 a = Jr[k];
            float4 b = M4[k];
            sum += a.x * b.x + a.y * b.y + a.z * b.z + a.w * b.w;
        }
        #pragma unroll
        for (int off = 16; off; off >>= 1)
            sum += __shfl_xor_sync(FULLM, sum, off);
        __shared__ float ws[8];
        const int lane = threadIdx.x & 31;
        const int wid  = threadIdx.x >> 5;
        if (lane == 0) ws[wid] = sum;
        __syncthreads();
        if (threadIdx.x == 0) {
            float tot = 0.0f;
            #pragma unroll
            for (int w = 0; w < 8; w++) tot += ws[w];
            g_F[row] = tot + h[row];
        }
    } else if (bid < NN + NWIN) {
        const int w = bid - NN;
        for (int e = threadIdx.x; e < W * W; e += 256) {
            const int k = e >> 6;
            const int l = e & 63;
            const int il = idx[w * W + l];
            const int ik = idx[w * W + k];
            g_Jw[(size_t)w * W * W + e] = J[(size_t)ik * NN + il];
            float jc = 0.0f;
            if (w > 0) {
                const int ikp = idx[(w - 1) * W + k];
                jc = J[(size_t)ikp * NN + il];
            }
            g_Jc[(size_t)w * W * W + e] = jc;
        }
    } else {
        const int t = (bid - NN - NWIN) * 256 + threadIdx.x;
        if (t < NSTEPS) {
            const float r = 2.0f * u[t] - 1.0f;
            g_TI[t] = make_float2(atanhf(r), __int_as_float(idx[t]));
        }
    }
}

// ---------------------------------------------------------------------------
__global__ __launch_bounds__(TPB, 1)
void pbit_dynamics(const float* __restrict__ J,
                   const float* __restrict__ m0,
                   float*       __restrict__ out) {
    extern __shared__ char smraw[];
    Sm* S = reinterpret_cast<Sm*>(smraw);

    const int tid  = threadIdx.x;
    const int lane = tid & 31;
    const bool is_ev = (tid < 32);
    const int oid  = tid - 32;      // owner index [0,512)

    // ---- init ----
    const float4* gF4 = reinterpret_cast<const float4*>(g_F);
    float4* F4 = reinterpret_cast<float4*>(S->F);
    float4 Fa, Fb;
    if (!is_ev) {
        Fa = gF4[oid];
        Fb = gF4[oid + NOWN];
        F4[oid]        = Fa;
        F4[oid + NOWN] = Fb;
    }
    for (int k = tid; k < NN; k += TPB)
        S->m[k] = (m0[k] > 0.0f) ? 1 : -1;
    if (tid == 0) { S->fcnt[0] = 0; S->fcnt[1] = 0; }
    for (int e = tid; e < W * W; e += TPB) {       // stage window 0
        S->Jw[0][e] = g_Jw[e];
        S->Jc[0][e] = g_Jc[e];
    }
    float2 tiPF0 = make_float2(0.f, 0.f), tiPF1 = tiPF0;
    if (is_ev) {
        tiPF0 = g_TI[lane];
        tiPF1 = g_TI[32 + lane];
    }
    unsigned prevM0 = 0, prevS0 = 0, prevM1 = 0, prevS1 = 0;
    __syncthreads();

    for (int p = 0; p < NWIN; p++) {
        const int par = p & 1;
        if (is_ev) {
            // ================= evaluator =================
            const float thr0 = tiPF0.x;
            const int   i0   = __float_as_int(tiPF0.y);
            const float thr1 = tiPF1.x;
            const int   i1x  = __float_as_int(tiPF1.y);
            float f0  = S->F[i0];            // state <= p-2
            float f1v = S->F[i1x];
            bool pos0 = (S->m[i0]  > 0);
            bool pos1 = (S->m[i1x] > 0);
            asm volatile("bar.arrive 1, %0;" :: "r"(TPB));   // release F_sh

            if (p + 1 < NWIN) {
                tiPF0 = g_TI[(p + 1) * W + lane];
                tiPF1 = g_TI[(p + 1) * W + 32 + lane];
            }

            // ---- catch up window p-1's flips (ascending step order) ----
            const float* TcP = S->Jc[par];
            {
                unsigned mm = prevM0;
                while (mm) {
                    const int k = __ffs(mm) - 1;
                    mm &= mm - 1;
                    const float dk = ((prevS0 >> k) & 1u) ? 2.0f : -2.0f;
                    f0  = fmaf(TcP[(k << 6) + lane],      dk, f0);
                    f1v = fmaf(TcP[(k << 6) + 32 + lane], dk, f1v);
                }
                mm = prevM1;
                while (mm) {
                    const int k = __ffs(mm) - 1;
                    mm &= mm - 1;
                    const int r = 32 + k;
                    const float dk = ((prevS1 >> k) & 1u) ? 2.0f : -2.0f;
                    f0  = fmaf(TcP[(r << 6) + lane],      dk, f0);
                    f1v = fmaf(TcP[(r << 6) + 32 + lane], dk, f1v);
                }
            }

            const float* TwP = S->Jw[par];
            unsigned nM0 = 0, nS0 = 0, nM1 = 0, nS1 = 0;
            int cnt = 0;

            // ---- half A: steps 0..31 ----
            {
                bool sp = (f0 >= thr0);
                bool fl = sp != pos0;
                unsigned fb  = __ballot_sync(FULLM, fl);
                unsigned sbm = __ballot_sync(FULLM, sp);
                while (fb) {
                    const int  f = __ffs(fb) - 1;
                    const bool s1 = (sbm >> f) & 1u;
                    const float d = s1 ? 2.0f : -2.0f;
                    const float jva = TwP[(f << 6) + lane];
                    const float jvb = TwP[(f << 6) + 32 + lane];
                    const int   ii  = __shfl_sync(FULLM, i0, f);
                    if (lane == f) {
                        S->m[ii] = s1 ? 1 : -1;
                        S->flist[par][cnt] = ii | (s1 ? (1 << 30) : 0);
                    }
                    nM0 |= 1u << f;
                    if (s1) nS0 |= 1u << f;
                    cnt++;
                    f0  = fmaf(jva, d, f0);
                    f1v = fmaf(jvb, d, f1v);
                    if (i0  == ii) pos0 = s1;
                    if (i1x == ii) pos1 = s1;
                    bool ns = false, nf2 = false;
                    if (lane > f) {
                        ns  = (f0 >= thr0);
                        nf2 = ns != pos0;
                    }
                    fb  = __ballot_sync(FULLM, nf2);
                    sbm = __ballot_sync(FULLM, ns);
                }
            }
            // ---- half B: steps 32..63 ----
            {
                bool sp = (f1v >= thr1);
                bool fl = sp != pos1;
                unsigned fb  = __ballot_sync(FULLM, fl);
                unsigned sbm = __ballot_sync(FULLM, sp);
                while (fb) {
                    const int  f = __ffs(fb) - 1;
                    const bool s1 = (sbm >> f) & 1u;
                    const float d = s1 ? 2.0f : -2.0f;
                    const int  r = 32 + f;
                    const float jvb = TwP[(r << 6) + 32 + lane];
                    const int   ii  = __shfl_sync(FULLM, i1x, f);
                    if (lane == f) {
                        S->m[ii] = s1 ? 1 : -1;
                        S->flist[par][cnt] = ii | (s1 ? (1 << 30) : 0);
                    }
                    nM1 |= 1u << f;
                    if (s1) nS1 |= 1u << f;
                    cnt++;
                    f1v = fmaf(jvb, d, f1v);
                    if (i1x == ii) pos1 = s1;
                    bool ns = false, nf2 = false;
                    if (lane > f) {
                        ns  = (f1v >= thr1);
                        nf2 = ns != pos1;
                    }
                    fb  = __ballot_sync(FULLM, nf2);
                    sbm = __ballot_sync(FULLM, ns);
                }
            }
            if (lane == 0) S->fcnt[par] = cnt;
            prevM0 = nM0; prevS0 = nS0;
            prevM1 = nM1; prevS1 = nS1;
        } else {
            // ================= owners =================
            // issue staging loads for window p+1 FIRST (latency hidden)
            float4 sw0, sw1, sc0, sc1;
            const bool hasStage = (p + 1 < NWIN);
            if (hasStage) {
                const float4* __restrict__ sw =
                    reinterpret_cast<const float4*>(g_Jw + (size_t)(p + 1) * (W * W));
                const float4* __restrict__ sc =
                    reinterpret_cast<const float4*>(g_Jc + (size_t)(p + 1) * (W * W));
                sw0 = sw[oid]; sw1 = sw[oid + NOWN];
                sc0 = sc[oid]; sc1 = sc[oid + NOWN];
            }

            // apply window p-1's flips (batch 8 -> 16 LDG.128 in flight)
            const int np = S->fcnt[par ^ 1];
            for (int kb = 0; kb < np; kb += 8) {
                float  dd[8];
                float4 r0[8], r1[8];
                #pragma unroll
                for (int j = 0; j < 8; j++) {
                    const bool v = (kb + j < np);
                    const int e = v ? S->flist[par ^ 1][kb + j] : 0;
                    dd[j] = v ? ((e & (1 << 30)) ? 2.0f : -2.0f) : 0.0f;
                    const int ik = e & 0xFFFF;
                    const float4* __restrict__ Jr =
                        reinterpret_cast<const float4*>(J) + (size_t)ik * (NN / 4);
                    if (v) {
                        r0[j] = Jr[oid];
                        r1[j] = Jr[oid + NOWN];
                    } else {
                        r0[j] = make_float4(0.f, 0.f, 0.f, 0.f);
                        r1[j] = r0[j];
                    }
                }
                #pragma unroll
                for (int j = 0; j < 8; j++) {
                    Fa.x = fmaf(r0[j].x, dd[j], Fa.x);
                    Fa.y = fmaf(r0[j].y, dd[j], Fa.y);
                    Fa.z = fmaf(r0[j].z, dd[j], Fa.z);
                    Fa.w = fmaf(r0[j].w, dd[j], Fa.w);
                    Fb.x = fmaf(r1[j].x, dd[j], Fb.x);
                    Fb.y = fmaf(r1[j].y, dd[j], Fb.y);
                    Fb.z = fmaf(r1[j].z, dd[j], Fb.z);
                    Fb.w = fmaf(r1[j].w, dd[j], Fb.w);
                }
            }

            // store staging into the buffer freed last window
            if (hasStage) {
                float4* dw = reinterpret_cast<float4*>(S->Jw[par ^ 1]);
                float4* dc = reinterpret_cast<float4*>(S->Jc[par ^ 1]);
                dw[oid] = sw0; dw[oid + NOWN] = sw1;
                dc[oid] = sc0; dc[oid + NOWN] = sc1;
            }

            // wait for evaluator's F_sh reads, then publish
            asm volatile("bar.sync 1, %0;" :: "r"(TPB));
            if (np > 0) {
                F4[oid]        = Fa;
                F4[oid + NOWN] = Fb;
            }
        }
        __syncthreads();
    }

    for (int k = tid; k < NN; k += TPB)
        out[k] = (float)S->m[k];
}

// ---------------------------------------------------------------------------
extern "C" void kernel_launch(void* const* d_in, const int* in_sizes, int n_in,
                              void* d_out, int out_size) {
    const float* J  = (const float*)d_in[0];
    const float* h  = (const float*)d_in[1];
    const float* m0 = (const float*)d_in[2];
    const int*   idx= (const int*)  d_in[3];
    const float* u  = (const float*)d_in[4];
    float* out = (float*)d_out;

    static bool attrSet = false;
    if (!attrSet) {
        cudaFuncSetAttribute(pbit_dynamics,
                             cudaFuncAttributeMaxDynamicSharedMemorySize,
                             SMEM_BYTES);
        attrSet = true;
    }

    const int prepBlocks = NN + NWIN + (NSTEPS + 255) / 256;
    prep_all<<<prepBlocks, 256>>>(J, h, m0, idx, u);
    pbit_dynamics<<<1, TPB, SMEM_BYTES>>>(J, m0, out);
}